// round 1
// baseline (speedup 1.0000x reference)
#include <cuda_runtime.h>

// Problem constants
#define NB 64
#define CI 256
#define TT 64
#define VV 25
#define O2 512     // 2*out_planes
#define GG 8
#define RW 49      // 2V-1
#define EPSV 1e-5f

// ---------------- scratch (static device globals; no runtime alloc) -------------
__device__ float g_y[NB*CI*VV];                // mean over T           (1.6 MB)
__device__ float g_qkv[NB*O2*VV];              // raw qkv projection    (3.3 MB)
__device__ float g_qsum[O2], g_qsq[O2], g_qscale[O2], g_qbias[O2];
__device__ float g_stk[NB*GG*3*625];           // qk/qr/kr raw          (3.84 MB)
__device__ float g_ssum[24], g_ssq[24], g_sscale[24], g_sbias[24];
__device__ float g_so[NB*O2*VV];               // sv/sve interleaved    (3.3 MB)
__device__ float g_osum[O2], g_osq[O2], g_oscale[O2], g_obias[O2];
__device__ float g_mult[NB*CI*VV];             // 1 + sigmoid(o)        (1.6 MB)

// ---------------- K0: zero stat accumulators (must be re-done every replay) ----
__global__ void k0_zero() {
    int t = threadIdx.x;
    for (int i = t; i < O2; i += 256) { g_qsum[i] = 0.f; g_qsq[i] = 0.f; g_osum[i] = 0.f; g_osq[i] = 0.f; }
    if (t < 24) { g_ssum[t] = 0.f; g_ssq[t] = 0.f; }
}

// ---------------- K1: y[n,c,v] = mean_t x[n,c,t,v] ------------------------------
// 800 threads = 4 slabs of 200. pos in [0,200): since 200 % 25 == 0, v = pos%25 is
// invariant over the 8 strided loads -> perfectly coalesced scalar streaming.
__global__ void __launch_bounds__(800) k1_mean(const float* __restrict__ x) {
    __shared__ float red[800];
    int tid = threadIdx.x;
    int sl = tid / 200, pos = tid % 200;
    int slab = blockIdx.x * 4 + sl;            // (n,c) slab index, < 16384
    const float* p = x + slab * 1600 + pos;
    float s = 0.f;
#pragma unroll
    for (int k = 0; k < 8; k++) s += p[200 * k];
    red[tid] = s;
    __syncthreads();
    if (pos < 25) {
        float tot = 0.f;
#pragma unroll
        for (int r = 0; r < 8; r++) tot += red[sl * 200 + r * 25 + pos];
        g_y[slab * 25 + pos] = tot * (1.0f / 64.0f);
    }
}

// ---------------- K2: qkv[n,o,v] = sum_c w[o,c] * y[n,c,v] + BN partial stats ---
// 128 blocks: (n, half of o). Each thread owns one o, 25 accumulators held as
// 14 packed f32x2 pairs; inner loop = 1 LDS(w) + 7 LDS.128(y,broadcast) + 14 FFMA2.
__global__ void __launch_bounds__(256) k2_qkv(const float* __restrict__ w) {
    __shared__ __align__(16) float ysm[CI * 28];  // rows padded 25 -> 28 (16B aligned)
    __shared__ float wsm[16 * 256];
    int tid = threadIdx.x;
    int n = blockIdx.x >> 1, half = blockIdx.x & 1;

    for (int i = tid; i < CI * 28; i += 256) ysm[i] = 0.f;
    __syncthreads();
    const float* yb = g_y + n * (CI * VV);
    for (int i = tid; i < CI * VV; i += 256) { int c = i / 25, v = i - c * 25; ysm[c * 28 + v] = yb[i]; }

    unsigned long long acc[14];
#pragma unroll
    for (int p = 0; p < 14; p++) acc[p] = 0ull;

    int o = half * 256 + tid;
    for (int c0 = 0; c0 < 256; c0 += 16) {
        __syncthreads();   // also separates ysm fill from first compute
        for (int i = tid; i < 4096; i += 256) {
            int ol = i >> 4, cc = i & 15;
            wsm[cc * 256 + ol] = w[(half * 256 + ol) * 256 + c0 + cc];
        }
        __syncthreads();
#pragma unroll
        for (int cc = 0; cc < 16; cc++) {
            float wv = wsm[cc * 256 + tid];
            unsigned long long w2; asm("mov.b64 %0,{%1,%1};" : "=l"(w2) : "f"(wv));
            const float4* yr = (const float4*)(ysm + (c0 + cc) * 28);
#pragma unroll
            for (int q = 0; q < 7; q++) {
                float4 yv = yr[q];
                unsigned long long y0, y1;
                asm("mov.b64 %0,{%1,%2};" : "=l"(y0) : "f"(yv.x), "f"(yv.y));
                asm("mov.b64 %0,{%1,%2};" : "=l"(y1) : "f"(yv.z), "f"(yv.w));
                asm("fma.rn.f32x2 %0,%1,%2,%0;" : "+l"(acc[2 * q])     : "l"(w2), "l"(y0));
                asm("fma.rn.f32x2 %0,%1,%2,%0;" : "+l"(acc[2 * q + 1]) : "l"(w2), "l"(y1));
            }
        }
    }
    float vals[28];
#pragma unroll
    for (int p = 0; p < 14; p++) {
        asm("mov.b64 {%0,%1},%2;" : "=f"(vals[2 * p]), "=f"(vals[2 * p + 1]) : "l"(acc[p]));
    }
    float s = 0.f, sq = 0.f;
    float* qb = g_qkv + n * (O2 * VV) + o * 25;
#pragma unroll
    for (int v = 0; v < 25; v++) { float q = vals[v]; qb[v] = q; s += q; sq += q * q; }
    atomicAdd(&g_qsum[o], s);
    atomicAdd(&g_qsq[o], sq);
}

// ---------------- K3: finalize qkv BN (per-channel over N*V = 1600) -------------
__global__ void k3_qstats(const float* __restrict__ gg, const float* __restrict__ bb) {
    int t = threadIdx.x;  // 512
    float m = g_qsum[t] * (1.f / 1600.f);
    float var = g_qsq[t] * (1.f / 1600.f) - m * m;
    float rs = rsqrtf(var + EPSV);
    float sc = rs * gg[t];
    g_qscale[t] = sc;
    g_qbias[t] = bb[t] - m * sc;
}

// ---------------- K4: stacked = {qk, qr, kr} per (n,g) + sim BN partial stats ---
__global__ void __launch_bounds__(256) k4_sim(const float* __restrict__ rel) {
    __shared__ float qs[16 * 25], ks[16 * 25], rs[32 * 49];
    __shared__ float ssum[3], ssq[3];
    int tid = threadIdx.x;
    int n = blockIdx.x >> 3, g = blockIdx.x & 7;
    int gb = g * 64;
    const float* qkvb = g_qkv + n * (O2 * VV) + gb * 25;
    for (int i = tid; i < 400; i += 256) { int c = i / 25; qs[i] = qkvb[i] * g_qscale[gb + c] + g_qbias[gb + c]; }
    for (int i = tid; i < 400; i += 256) { int c = i / 25; ks[i] = qkvb[400 + i] * g_qscale[gb + 16 + c] + g_qbias[gb + 16 + c]; }
    for (int i = tid; i < 1568; i += 256) rs[i] = rel[i];
    if (tid < 3) { ssum[tid] = 0.f; ssq[tid] = 0.f; }
    __syncthreads();

    float sa = 0.f, qa = 0.f, sb2 = 0.f, qb2 = 0.f, sc2 = 0.f, qc2 = 0.f;
    float* ob = g_stk + blockIdx.x * 1875;
    for (int e = tid; e < 625; e += 256) {
        int i = e / 25, j = e - i * 25;
        float a = 0.f, b = 0.f, c2 = 0.f;
        int di = i - j + 24, dj = j - i + 24;
#pragma unroll
        for (int c = 0; c < 16; c++) {
            float qv = qs[c * 25 + i], kv = ks[c * 25 + j];
            a  += qv * kv;
            b  += qv * rs[c * 49 + di];
            c2 += kv * rs[(16 + c) * 49 + dj];
        }
        ob[e] = a; ob[625 + e] = b; ob[1250 + e] = c2;
        sa += a; qa += a * a; sb2 += b; qb2 += b * b; sc2 += c2; qc2 += c2 * c2;
    }
    atomicAdd(&ssum[0], sa);  atomicAdd(&ssq[0], qa);
    atomicAdd(&ssum[1], sb2); atomicAdd(&ssq[1], qb2);
    atomicAdd(&ssum[2], sc2); atomicAdd(&ssq[2], qc2);
    __syncthreads();
    if (tid < 3) { atomicAdd(&g_ssum[tid * 8 + g], ssum[tid]); atomicAdd(&g_ssq[tid * 8 + g], ssq[tid]); }
}

// ---------------- K5: finalize sim BN (per-channel over N*V*V = 40000) ----------
__global__ void k5_sstats(const float* __restrict__ gg, const float* __restrict__ bb) {
    int t = threadIdx.x;
    if (t < 24) {
        float m = g_ssum[t] * (1.f / 40000.f);
        float var = g_ssq[t] * (1.f / 40000.f) - m * m;
        float rs = rsqrtf(var + EPSV);
        float sc = rs * gg[t];
        g_sscale[t] = sc;
        g_sbias[t] = bb[t] - m * sc;
    }
}

// ---------------- K6: softmax + sv/sve per (n,g) + out BN partial stats ---------
__global__ void __launch_bounds__(256) k6_attn(const float* __restrict__ rel) {
    __shared__ float sim[25 * 26];
    __shared__ float vs[32 * 25];
    __shared__ float rv[32 * 49];
    __shared__ float rinv[25];
    __shared__ float csum[64], csq[64];
    int tid = threadIdx.x;
    int n = blockIdx.x >> 3, g = blockIdx.x & 7;
    int gb = g * 64;

    const float* qkvb = g_qkv + n * (O2 * VV) + (gb + 32) * 25;
    for (int i = tid; i < 800; i += 256) { int c = i / 25; vs[i] = qkvb[i] * g_qscale[gb + 32 + c] + g_qbias[gb + 32 + c]; }
    for (int i = tid; i < 1568; i += 256) rv[i] = rel[32 * 49 + i];
    if (tid < 64) { csum[tid] = 0.f; csq[tid] = 0.f; }

    float sc0 = g_sscale[g],      b0 = g_sbias[g];
    float sc1 = g_sscale[8 + g],  b1 = g_sbias[8 + g];
    float sc2 = g_sscale[16 + g], b2 = g_sbias[16 + g];
    const float* sb = g_stk + blockIdx.x * 1875;
    for (int e = tid; e < 625; e += 256) {
        int i = e / 25, j = e - i * 25;
        float s = sb[e] * sc0 + b0 + sb[625 + e] * sc1 + b1 + sb[1250 + e] * sc2 + b2;
        sim[i * 26 + j] = s;
    }
    __syncthreads();
    if (tid < 25) {
        float m = -1e30f;
        for (int j = 0; j < 25; j++) m = fmaxf(m, sim[tid * 26 + j]);
        float s = 0.f;
        for (int j = 0; j < 25; j++) { float e2 = expf(sim[tid * 26 + j] - m); sim[tid * 26 + j] = e2; s += e2; }
        rinv[tid] = 1.f / s;
    }
    __syncthreads();
    for (int e = tid; e < 625; e += 256) { int i = e / 25, j = e - i * 25; sim[i * 26 + j] *= rinv[i]; }
    __syncthreads();

    float* sob = g_so + n * (O2 * VV) + gb * 25;
    for (int idx = tid; idx < 800; idx += 256) {
        int c = idx / 25, i = idx - c * 25;
        float sv = 0.f, se = 0.f;
#pragma unroll
        for (int j = 0; j < 25; j++) {
            float wv = sim[i * 26 + j];
            sv += wv * vs[c * 25 + j];
            se += wv * rv[c * 49 + (i - j + 24)];
        }
        sob[(2 * c) * 25 + i] = sv;
        sob[(2 * c + 1) * 25 + i] = se;
        atomicAdd(&csum[2 * c], sv);     atomicAdd(&csq[2 * c], sv * sv);
        atomicAdd(&csum[2 * c + 1], se); atomicAdd(&csq[2 * c + 1], se * se);
    }
    __syncthreads();
    if (tid < 64) { atomicAdd(&g_osum[gb + tid], csum[tid]); atomicAdd(&g_osq[gb + tid], csq[tid]); }
}

// ---------------- K7a: finalize out BN (per-channel over N*V = 1600) ------------
__global__ void k7a_ostats(const float* __restrict__ gg, const float* __restrict__ bb) {
    int t = threadIdx.x;  // 512
    float m = g_osum[t] * (1.f / 1600.f);
    float var = g_osq[t] * (1.f / 1600.f) - m * m;
    float rs = rsqrtf(var + EPSV);
    float sc = rs * gg[t];
    g_oscale[t] = sc;
    g_obias[t] = bb[t] - m * sc;
}

// ---------------- K7b: gate multiplier = 1 + sigmoid(bn(sv)+bn(sve)) ------------
__global__ void k7b_mult() {
    int e = blockIdx.x * 256 + threadIdx.x;  // < 409600 exact
    int n = e / 6400, r = e - n * 6400;
    int p = r / 25, i = r - p * 25;
    const float* sb = g_so + n * 12800 + (2 * p) * 25;
    float a = sb[i]      * g_oscale[2 * p]     + g_obias[2 * p];
    float b = sb[25 + i] * g_oscale[2 * p + 1] + g_obias[2 * p + 1];
    float v = a + b;
    g_mult[e] = 1.f + 1.f / (1.f + expf(-v));
}

// ---------------- K8: out[n,c,t,v] = x * mult[n,c,v] (streaming) ----------------
__global__ void __launch_bounds__(800) k8_out(const float* __restrict__ x, float* __restrict__ out) {
    int tid = threadIdx.x;
    int sl = tid / 200, pos = tid % 200;
    int slab = blockIdx.x * 4 + sl;
    float m = g_mult[slab * 25 + pos % 25];   // v invariant: 200 % 25 == 0
    const float* xp = x + slab * 1600 + pos;
    float* op = out + slab * 1600 + pos;
#pragma unroll
    for (int k = 0; k < 8; k++) op[200 * k] = xp[200 * k] * m;
}

// ---------------- launch ---------------------------------------------------------
extern "C" void kernel_launch(void* const* d_in, const int* in_sizes, int n_in,
                              void* d_out, int out_size) {
    const float* x   = (const float*)d_in[0];
    const float* w   = (const float*)d_in[1];
    const float* rel = (const float*)d_in[2];
    const float* qg  = (const float*)d_in[3];
    const float* qb  = (const float*)d_in[4];
    const float* sg  = (const float*)d_in[5];
    const float* sbb = (const float*)d_in[6];
    const float* og  = (const float*)d_in[7];
    const float* ob  = (const float*)d_in[8];
    float* out = (float*)d_out;

    k0_zero<<<1, 256>>>();
    k1_mean<<<4096, 800>>>(x);
    k2_qkv<<<128, 256>>>(w);
    k3_qstats<<<1, 512>>>(qg, qb);
    k4_sim<<<512, 256>>>(rel);
    k5_sstats<<<1, 32>>>(sg, sbb);
    k6_attn<<<512, 256>>>(rel);
    k7a_ostats<<<1, 512>>>(og, ob);
    k7b_mult<<<1600, 256>>>();
    k8_out<<<4096, 800>>>(x, out);
}

// round 2
// speedup vs baseline: 1.0800x; 1.0800x over previous
#include <cuda_runtime.h>

#define EPSV 1e-5f

// ---------------- scratch (static device globals; no runtime alloc) -------------
__device__ float g_y[64*256*25];               // mean over T
__device__ float g_qkv[64*512*25];             // raw qkv projection
__device__ float g_qsum[512], g_qsq[512];
__device__ float g_stk[64*8*3*625];            // qk/qr/kr raw
__device__ float g_ssum[24], g_ssq[24];
__device__ float g_so[64*512*25];              // sv/sve interleaved
__device__ float g_osum[512], g_osq[512];

// ---------------- K1: y[n,c,v] = mean_t x[n,c,t,v]  (float4, MLP=4) -------------
// 400 threads = 4 slabs x 100. Each thread: 4 x LDG.128 at stride 400 floats
// (= 16 t-steps exactly, so each float4 lane has a FIXED v = (4p+k)%25).
// Block 0 additionally zeroes all stat accumulators (safe: k2/k4/k6 are later
// kernels in stream order, so the whole k1 grid completes first).
__global__ void __launch_bounds__(400) k1_mean(const float* __restrict__ x) {
    __shared__ float red[1600];
    int tid = threadIdx.x;
    if (blockIdx.x == 0) {
        for (int i = tid; i < 512; i += 400) { g_qsum[i]=0.f; g_qsq[i]=0.f; g_osum[i]=0.f; g_osq[i]=0.f; }
        if (tid < 24) { g_ssum[tid]=0.f; g_ssq[tid]=0.f; }
    }
    int sg = tid / 100, p = tid % 100;
    int slab = blockIdx.x * 4 + sg;                 // (n,c) index < 16384
    const float4* xp = (const float4*)(x + slab * 1600) + p;
    float4 a0 = xp[0], a1 = xp[100], a2 = xp[200], a3 = xp[300];
    float4 s = make_float4(a0.x+a1.x+a2.x+a3.x, a0.y+a1.y+a2.y+a3.y,
                           a0.z+a1.z+a2.z+a3.z, a0.w+a1.w+a2.w+a3.w);
    ((float4*)red)[sg*100 + p] = s;                 // STS.128
    __syncthreads();
    if (p < 25) {
        float tot = 0.f;
#pragma unroll
        for (int r = 0; r < 16; r++) tot += red[sg*400 + p + 25*r];  // (p+25r)%25==p ✓
        g_y[slab*25 + p] = tot * (1.0f/64.0f);
    }
}

// ---------------- K2: qkv[n,o,v] = sum_c w[o,c]*y[n,c,v] + BN partial stats -----
// 128 blocks (n, half-of-o), thread owns one o; 25 accumulators as 14 b64 pairs.
// ysm rows padded 25->28 floats (112B = 7x16B, alignment holds); loaded as
// ulonglong2 so one LDS.128 directly yields two f32x2 operands (no mov.b64).
__global__ void __launch_bounds__(256) k2_qkv(const float* __restrict__ w) {
    __shared__ __align__(16) float ysm[256*28];
    __shared__ float wsm[16*256];
    int tid = threadIdx.x;
    int n = blockIdx.x >> 1, half = blockIdx.x & 1;

    for (int i = tid; i < 256*28; i += 256) ysm[i] = 0.f;
    __syncthreads();
    const float* yb = g_y + n * (256*25);
    for (int i = tid; i < 256*25; i += 256) { int c = i/25, v = i - c*25; ysm[c*28 + v] = yb[i]; }

    unsigned long long acc[14];
#pragma unroll
    for (int q = 0; q < 14; q++) acc[q] = 0ull;

    int o = half * 256 + tid;
    for (int c0 = 0; c0 < 256; c0 += 16) {
        __syncthreads();
        for (int i = tid; i < 4096; i += 256) {
            int ol = i >> 4, cc = i & 15;
            wsm[cc*256 + ol] = w[(half*256 + ol)*256 + c0 + cc];
        }
        __syncthreads();
#pragma unroll
        for (int cc = 0; cc < 16; cc++) {
            float wv = wsm[cc*256 + tid];
            unsigned long long w2; asm("mov.b64 %0,{%1,%1};" : "=l"(w2) : "f"(wv));
            const ulonglong2* yr = (const ulonglong2*)(ysm + (c0 + cc)*28);
#pragma unroll
            for (int q = 0; q < 7; q++) {
                ulonglong2 yv = yr[q];
                asm("fma.rn.f32x2 %0,%1,%2,%0;" : "+l"(acc[2*q])   : "l"(w2), "l"(yv.x));
                asm("fma.rn.f32x2 %0,%1,%2,%0;" : "+l"(acc[2*q+1]) : "l"(w2), "l"(yv.y));
            }
        }
    }
    float vals[28];
#pragma unroll
    for (int q = 0; q < 14; q++)
        asm("mov.b64 {%0,%1},%2;" : "=f"(vals[2*q]), "=f"(vals[2*q+1]) : "l"(acc[q]));

    float s = 0.f, sq = 0.f;
    float* qb = g_qkv + n*(512*25) + o*25;
#pragma unroll
    for (int v = 0; v < 25; v++) { float q = vals[v]; qb[v] = q; s += q; sq += q*q; }
    atomicAdd(&g_qsum[o], s);
    atomicAdd(&g_qsq[o], sq);
}

// ---------------- K4: stacked = {qk,qr,kr} per (n,g); qkv-BN finalized inline ---
__global__ void __launch_bounds__(256) k4_sim(const float* __restrict__ rel,
                                              const float* __restrict__ qg,
                                              const float* __restrict__ qbb) {
    __shared__ float qs[400], ks[400], rs[1568];
    __shared__ float sc_[32], bi_[32];
    __shared__ float ssum[3], ssq[3];
    int tid = threadIdx.x;
    int n = blockIdx.x >> 3, g = blockIdx.x & 7;
    int gb = g * 64;
    if (tid < 32) {                                 // per-block BN finalize (q,k channels)
        int ch = gb + tid;
        float m = g_qsum[ch] * (1.f/1600.f);
        float var = g_qsq[ch] * (1.f/1600.f) - m*m;
        float s = rsqrtf(var + EPSV) * qg[ch];
        sc_[tid] = s; bi_[tid] = qbb[ch] - m*s;
    }
    if (tid < 3) { ssum[tid] = 0.f; ssq[tid] = 0.f; }
    __syncthreads();
    const float* qkvb = g_qkv + n*12800 + gb*25;
    for (int i = tid; i < 400; i += 256) { int c = i/25; qs[i] = qkvb[i]     *sc_[c]    + bi_[c]; }
    for (int i = tid; i < 400; i += 256) { int c = i/25; ks[i] = qkvb[400+i] *sc_[16+c] + bi_[16+c]; }
    for (int i = tid; i < 1568; i += 256) rs[i] = rel[i];
    __syncthreads();

    float sa=0.f, qa=0.f, sb2=0.f, qb2=0.f, sc2=0.f, qc2=0.f;
    float* ob = g_stk + blockIdx.x * 1875;
    for (int e = tid; e < 625; e += 256) {
        int i = e/25, j = e - i*25;
        float a=0.f, b=0.f, c2=0.f;
        int di = i - j + 24, dj = j - i + 24;
#pragma unroll
        for (int c = 0; c < 16; c++) {
            float qv = qs[c*25 + i], kv = ks[c*25 + j];
            a  += qv * kv;
            b  += qv * rs[c*49 + di];
            c2 += kv * rs[(16+c)*49 + dj];
        }
        ob[e] = a; ob[625+e] = b; ob[1250+e] = c2;
        sa += a; qa += a*a; sb2 += b; qb2 += b*b; sc2 += c2; qc2 += c2*c2;
    }
    atomicAdd(&ssum[0], sa);  atomicAdd(&ssq[0], qa);
    atomicAdd(&ssum[1], sb2); atomicAdd(&ssq[1], qb2);
    atomicAdd(&ssum[2], sc2); atomicAdd(&ssq[2], qc2);
    __syncthreads();
    if (tid < 3) { atomicAdd(&g_ssum[tid*8 + g], ssum[tid]); atomicAdd(&g_ssq[tid*8 + g], ssq[tid]); }
}

// ---------------- K6: softmax + sv/sve; sim-BN and v-channel BN inline ----------
__global__ void __launch_bounds__(256) k6_attn(const float* __restrict__ rel,
                                               const float* __restrict__ qg,
                                               const float* __restrict__ qbb,
                                               const float* __restrict__ sg,
                                               const float* __restrict__ sbb) {
    __shared__ float sim[25*26];
    __shared__ float vs[800], rv[1568], rinv[25];
    __shared__ float csum[64], csq[64];
    __shared__ float vsc[32], vbi[32], ssc[3], sbi[3];
    int tid = threadIdx.x;
    int n = blockIdx.x >> 3, g = blockIdx.x & 7;
    int gb = g * 64;

    if (tid < 32) {                                 // BN finalize for v channels
        int ch = gb + 32 + tid;
        float m = g_qsum[ch] * (1.f/1600.f);
        float var = g_qsq[ch] * (1.f/1600.f) - m*m;
        float s = rsqrtf(var + EPSV) * qg[ch];
        vsc[tid] = s; vbi[tid] = qbb[ch] - m*s;
    } else if (tid < 35) {                          // sim BN finalize (3 channels)
        int t2 = tid - 32, ch = t2*8 + g;
        float m = g_ssum[ch] * (1.f/40000.f);
        float var = g_ssq[ch] * (1.f/40000.f) - m*m;
        float s = rsqrtf(var + EPSV) * sg[ch];
        ssc[t2] = s; sbi[t2] = sbb[ch] - m*s;
    }
    if (tid < 64) { csum[tid] = 0.f; csq[tid] = 0.f; }
    __syncthreads();

    const float* qkvb = g_qkv + n*12800 + (gb + 32)*25;
    for (int i = tid; i < 800; i += 256) { int c = i/25; vs[i] = qkvb[i]*vsc[c] + vbi[c]; }
    for (int i = tid; i < 1568; i += 256) rv[i] = rel[32*49 + i];

    const float* sb = g_stk + blockIdx.x * 1875;
    for (int e = tid; e < 625; e += 256) {
        int i = e/25, j = e - i*25;
        float s = sb[e]*ssc[0] + sbi[0] + sb[625+e]*ssc[1] + sbi[1] + sb[1250+e]*ssc[2] + sbi[2];
        sim[i*26 + j] = s;
    }
    __syncthreads();
    if (tid < 25) {
        float m = -1e30f;
        for (int j = 0; j < 25; j++) m = fmaxf(m, sim[tid*26 + j]);
        float s = 0.f;
        for (int j = 0; j < 25; j++) { float e2 = expf(sim[tid*26 + j] - m); sim[tid*26 + j] = e2; s += e2; }
        rinv[tid] = 1.f / s;
    }
    __syncthreads();
    for (int e = tid; e < 625; e += 256) { int i = e/25, j = e - i*25; sim[i*26 + j] *= rinv[i]; }
    __syncthreads();

    float* sob = g_so + n*12800 + gb*25;
    for (int idx = tid; idx < 800; idx += 256) {
        int c = idx/25, i = idx - c*25;
        float sv = 0.f, se = 0.f;
#pragma unroll
        for (int j = 0; j < 25; j++) {
            float wv = sim[i*26 + j];
            sv += wv * vs[c*25 + j];
            se += wv * rv[c*49 + (i - j + 24)];
        }
        sob[(2*c)*25 + i]   = sv;
        sob[(2*c+1)*25 + i] = se;
        atomicAdd(&csum[2*c],   sv); atomicAdd(&csq[2*c],   sv*sv);
        atomicAdd(&csum[2*c+1], se); atomicAdd(&csq[2*c+1], se*se);
    }
    __syncthreads();
    if (tid < 64) { atomicAdd(&g_osum[gb + tid], csum[tid]); atomicAdd(&g_osq[gb + tid], csq[tid]); }
}

// ---------------- K8: out = x * (1 + sigmoid(o));  out-BN + gate inline ---------
// 400 threads = 4 slabs x 100, float4 streaming with 4 batched loads then stores.
__global__ void __launch_bounds__(400) k8_out(const float* __restrict__ x,
                                              float* __restrict__ out,
                                              const float* __restrict__ og,
                                              const float* __restrict__ ob) {
    __shared__ float msh[4][25];
    int tid = threadIdx.x;
    int sg = tid / 100, p = tid % 100;
    int slab = blockIdx.x * 4 + sg;
    int n = slab >> 8, c = slab & 255;
    if (p < 25) {
        int ch0 = 2*c, ch1 = ch0 + 1;
        float m0 = g_osum[ch0] * (1.f/1600.f);
        float v0 = g_osq[ch0] * (1.f/1600.f) - m0*m0;
        float s0 = rsqrtf(v0 + EPSV) * og[ch0];
        float b0 = ob[ch0] - m0*s0;
        float m1 = g_osum[ch1] * (1.f/1600.f);
        float v1 = g_osq[ch1] * (1.f/1600.f) - m1*m1;
        float s1 = rsqrtf(v1 + EPSV) * og[ch1];
        float b1 = ob[ch1] - m1*s1;
        const float* sb = g_so + n*12800 + ch0*25;
        float t = (sb[p]*s0 + b0) + (sb[25+p]*s1 + b1);
        msh[sg][p] = 1.f + 1.f/(1.f + expf(-t));
    }
    __syncthreads();
    int f0 = 4*p;
    float m0 = msh[sg][f0 % 25];
    float m1 = msh[sg][(f0+1) % 25];
    float m2 = msh[sg][(f0+2) % 25];
    float m3 = msh[sg][(f0+3) % 25];
    const float4* xp = (const float4*)(x + slab*1600) + p;
    float4* op = (float4*)(out + slab*1600) + p;
    float4 x0 = xp[0], x1 = xp[100], x2 = xp[200], x3 = xp[300];
    op[0]   = make_float4(x0.x*m0, x0.y*m1, x0.z*m2, x0.w*m3);
    op[100] = make_float4(x1.x*m0, x1.y*m1, x1.z*m2, x1.w*m3);
    op[200] = make_float4(x2.x*m0, x2.y*m1, x2.z*m2, x2.w*m3);
    op[300] = make_float4(x3.x*m0, x3.y*m1, x3.z*m2, x3.w*m3);
}

// ---------------- launch ---------------------------------------------------------
extern "C" void kernel_launch(void* const* d_in, const int* in_sizes, int n_in,
                              void* d_out, int out_size) {
    const float* x   = (const float*)d_in[0];
    const float* w   = (const float*)d_in[1];
    const float* rel = (const float*)d_in[2];
    const float* qg  = (const float*)d_in[3];
    const float* qb  = (const float*)d_in[4];
    const float* sg  = (const float*)d_in[5];
    const float* sbb = (const float*)d_in[6];
    const float* og  = (const float*)d_in[7];
    const float* ob  = (const float*)d_in[8];
    float* out = (float*)d_out;

    k1_mean<<<4096, 400>>>(x);
    k2_qkv<<<128, 256>>>(w);
    k4_sim<<<512, 256>>>(rel, qg, qb);
    k6_attn<<<512, 256>>>(rel, qg, qb, sg, sbb);
    k8_out<<<4096, 400>>>(x, out, og, ob);
}

// round 3
// speedup vs baseline: 1.4547x; 1.3469x over previous
#include <cuda_runtime.h>

#define EPSV 1e-5f

// ---------------- scratch (static device globals; no runtime alloc) -------------
__device__ float g_y[64*256*25];               // mean over T
__device__ float g_qkv[64*512*25];             // raw qkv projection
__device__ float g_qsum[512], g_qsq[512];
__device__ float g_stk[64*8*3*625];            // qk/qr/kr raw
__device__ float g_ssum[24], g_ssq[24];
__device__ float g_so[64*512*25];              // sv/sve interleaved
__device__ float g_osum[512], g_osq[512];

// ---------------- K1: y[n,c,v] = mean_t x[n,c,t,v]  (float4, MLP=8) -------------
// 400 threads, block covers 8 (n,c) slabs: thread handles the same 100-float4
// position in slab sg and slab sg+4 -> 8 independent LDG.128 front-batched.
__global__ void __launch_bounds__(400) k1_mean(const float* __restrict__ x) {
    __shared__ float redA[1600], redB[1600];
    int tid = threadIdx.x;
    if (blockIdx.x == 0) {
        for (int i = tid; i < 512; i += 400) { g_qsum[i]=0.f; g_qsq[i]=0.f; g_osum[i]=0.f; g_osq[i]=0.f; }
        if (tid < 24) { g_ssum[tid]=0.f; g_ssq[tid]=0.f; }
    }
    int sg = tid / 100, p = tid % 100;
    int s0 = blockIdx.x * 8 + sg, s1 = s0 + 4;
    const float4* xa = (const float4*)(x + s0 * 1600) + p;
    const float4* xb = (const float4*)(x + s1 * 1600) + p;
    float4 a0 = xa[0], a1 = xa[100], a2 = xa[200], a3 = xa[300];
    float4 b0 = xb[0], b1 = xb[100], b2 = xb[200], b3 = xb[300];
    float4 sa = make_float4(a0.x+a1.x+a2.x+a3.x, a0.y+a1.y+a2.y+a3.y,
                            a0.z+a1.z+a2.z+a3.z, a0.w+a1.w+a2.w+a3.w);
    float4 sb = make_float4(b0.x+b1.x+b2.x+b3.x, b0.y+b1.y+b2.y+b3.y,
                            b0.z+b1.z+b2.z+b3.z, b0.w+b1.w+b2.w+b3.w);
    ((float4*)redA)[sg*100 + p] = sa;
    ((float4*)redB)[sg*100 + p] = sb;
    __syncthreads();
    if (p < 25) {
        float t0 = 0.f, t1 = 0.f;
#pragma unroll
        for (int r = 0; r < 16; r++) { t0 += redA[sg*400 + p + 25*r]; t1 += redB[sg*400 + p + 25*r]; }
        g_y[s0*25 + p] = t0 * (1.0f/64.0f);
        g_y[s1*25 + p] = t1 * (1.0f/64.0f);
    }
}

// ---------------- K2: qkv[n,o,v] = sum_c w[o,c]*y[n,c,v] + BN partial stats -----
__global__ void __launch_bounds__(256) k2_qkv(const float* __restrict__ w) {
    __shared__ __align__(16) float ysm[256*28];
    __shared__ float wsm[16*256];
    int tid = threadIdx.x;
    int n = blockIdx.x >> 1, half = blockIdx.x & 1;

    for (int i = tid; i < 256*28; i += 256) ysm[i] = 0.f;
    __syncthreads();
    const float* yb = g_y + n * (256*25);
    for (int i = tid; i < 256*25; i += 256) { int c = i/25, v = i - c*25; ysm[c*28 + v] = yb[i]; }

    unsigned long long acc[14];
#pragma unroll
    for (int q = 0; q < 14; q++) acc[q] = 0ull;

    int o = half * 256 + tid;
    for (int c0 = 0; c0 < 256; c0 += 16) {
        __syncthreads();
        for (int i = tid; i < 4096; i += 256) {
            int ol = i >> 4, cc = i & 15;
            wsm[cc*256 + ol] = w[(half*256 + ol)*256 + c0 + cc];
        }
        __syncthreads();
#pragma unroll
        for (int cc = 0; cc < 16; cc++) {
            float wv = wsm[cc*256 + tid];
            unsigned long long w2; asm("mov.b64 %0,{%1,%1};" : "=l"(w2) : "f"(wv));
            const ulonglong2* yr = (const ulonglong2*)(ysm + (c0 + cc)*28);
#pragma unroll
            for (int q = 0; q < 7; q++) {
                ulonglong2 yv = yr[q];
                asm("fma.rn.f32x2 %0,%1,%2,%0;" : "+l"(acc[2*q])   : "l"(w2), "l"(yv.x));
                asm("fma.rn.f32x2 %0,%1,%2,%0;" : "+l"(acc[2*q+1]) : "l"(w2), "l"(yv.y));
            }
        }
    }
    float vals[28];
#pragma unroll
    for (int q = 0; q < 14; q++)
        asm("mov.b64 {%0,%1},%2;" : "=f"(vals[2*q]), "=f"(vals[2*q+1]) : "l"(acc[q]));

    float s = 0.f, sq = 0.f;
    float* qb = g_qkv + n*(512*25) + o*25;
#pragma unroll
    for (int v = 0; v < 25; v++) { float q = vals[v]; qb[v] = q; s += q; sq += q*q; }
    atomicAdd(&g_qsum[o], s);
    atomicAdd(&g_qsq[o], sq);
}

// ---------------- K4: stacked = {qk,qr,kr} per (n,g); warp-reduced stats --------
__global__ void __launch_bounds__(256) k4_sim(const float* __restrict__ rel,
                                              const float* __restrict__ qg,
                                              const float* __restrict__ qbb) {
    __shared__ float qs[400], ks[400], rs[1568];
    __shared__ float sc_[32], bi_[32];
    __shared__ float ssum[3], ssq[3];
    int tid = threadIdx.x;
    int n = blockIdx.x >> 3, g = blockIdx.x & 7;
    int gb = g * 64;
    if (tid < 32) {
        int ch = gb + tid;
        float m = g_qsum[ch] * (1.f/1600.f);
        float var = g_qsq[ch] * (1.f/1600.f) - m*m;
        float s = rsqrtf(var + EPSV) * qg[ch];
        sc_[tid] = s; bi_[tid] = qbb[ch] - m*s;
    }
    if (tid < 3) { ssum[tid] = 0.f; ssq[tid] = 0.f; }
    __syncthreads();
    const float* qkvb = g_qkv + n*12800 + gb*25;
    for (int i = tid; i < 400; i += 256) { int c = i/25; qs[i] = qkvb[i]     *sc_[c]    + bi_[c]; }
    for (int i = tid; i < 400; i += 256) { int c = i/25; ks[i] = qkvb[400+i] *sc_[16+c] + bi_[16+c]; }
    for (int i = tid; i < 1568; i += 256) rs[i] = rel[i];
    __syncthreads();

    float sa=0.f, qa=0.f, sb2=0.f, qb2=0.f, sc2=0.f, qc2=0.f;
    float* ob = g_stk + blockIdx.x * 1875;
    for (int e = tid; e < 625; e += 256) {
        int i = e/25, j = e - i*25;
        float a=0.f, b=0.f, c2=0.f;
        int di = i - j + 24, dj = j - i + 24;
#pragma unroll
        for (int c = 0; c < 16; c++) {
            float qv = qs[c*25 + i], kv = ks[c*25 + j];
            a  += qv * kv;
            b  += qv * rs[c*49 + di];
            c2 += kv * rs[(16+c)*49 + dj];
        }
        ob[e] = a; ob[625+e] = b; ob[1250+e] = c2;
        sa += a; qa += a*a; sb2 += b; qb2 += b*b; sc2 += c2; qc2 += c2*c2;
    }
    // warp-level reduction, then one shared atomic per warp
#pragma unroll
    for (int d = 16; d > 0; d >>= 1) {
        sa  += __shfl_xor_sync(0xffffffffu, sa,  d);
        qa  += __shfl_xor_sync(0xffffffffu, qa,  d);
        sb2 += __shfl_xor_sync(0xffffffffu, sb2, d);
        qb2 += __shfl_xor_sync(0xffffffffu, qb2, d);
        sc2 += __shfl_xor_sync(0xffffffffu, sc2, d);
        qc2 += __shfl_xor_sync(0xffffffffu, qc2, d);
    }
    if ((tid & 31) == 0) {
        atomicAdd(&ssum[0], sa);  atomicAdd(&ssq[0], qa);
        atomicAdd(&ssum[1], sb2); atomicAdd(&ssq[1], qb2);
        atomicAdd(&ssum[2], sc2); atomicAdd(&ssq[2], qc2);
    }
    __syncthreads();
    if (tid < 3) { atomicAdd(&g_ssum[tid*8 + g], ssum[tid]); atomicAdd(&g_ssq[tid*8 + g], ssq[tid]); }
}

// ---------------- K6: softmax + sv/sve; no per-element atomics ------------------
__global__ void __launch_bounds__(256) k6_attn(const float* __restrict__ rel,
                                               const float* __restrict__ qg,
                                               const float* __restrict__ qbb,
                                               const float* __restrict__ sg,
                                               const float* __restrict__ sbb) {
    __shared__ float sim[25*26];
    __shared__ float vs[800], rv[1568], rowsum[25], rinv[25];
    __shared__ float svsh[800], sesh[800];
    __shared__ float vsc[32], vbi[32], ssc[3], sbi[3];
    int tid = threadIdx.x;
    int n = blockIdx.x >> 3, g = blockIdx.x & 7;
    int gb = g * 64;

    if (tid < 32) {                                 // BN finalize for v channels
        int ch = gb + 32 + tid;
        float m = g_qsum[ch] * (1.f/1600.f);
        float var = g_qsq[ch] * (1.f/1600.f) - m*m;
        float s = rsqrtf(var + EPSV) * qg[ch];
        vsc[tid] = s; vbi[tid] = qbb[ch] - m*s;
    } else if (tid < 35) {                          // sim BN finalize (3 channels)
        int t2 = tid - 32, ch = t2*8 + g;
        float m = g_ssum[ch] * (1.f/40000.f);
        float var = g_ssq[ch] * (1.f/40000.f) - m*m;
        float s = rsqrtf(var + EPSV) * sg[ch];
        ssc[t2] = s; sbi[t2] = sbb[ch] - m*s;
    }
    if (tid < 25) rowsum[tid] = 0.f;
    __syncthreads();

    const float* qkvb = g_qkv + n*12800 + (gb + 32)*25;
    for (int i = tid; i < 800; i += 256) { int c = i/25; vs[i] = qkvb[i]*vsc[c] + vbi[c]; }
    for (int i = tid; i < 1568; i += 256) rv[i] = rel[32*49 + i];

    // exp over all 256 threads; BN'd logits are O(few sigma) so no max shift needed
    const float* sb = g_stk + blockIdx.x * 1875;
    for (int e = tid; e < 625; e += 256) {
        int i = e/25, j = e - i*25;
        float s = sb[e]*ssc[0] + sbi[0] + sb[625+e]*ssc[1] + sbi[1] + sb[1250+e]*ssc[2] + sbi[2];
        float ex = __expf(s);
        sim[i*26 + j] = ex;
        atomicAdd(&rowsum[i], ex);
    }
    __syncthreads();
    if (tid < 25) rinv[tid] = 1.f / rowsum[tid];
    __syncthreads();

    float* sob = g_so + n*12800 + gb*25;
    for (int idx = tid; idx < 800; idx += 256) {
        int c = idx/25, i = idx - c*25;
        float sv = 0.f, se = 0.f;
#pragma unroll
        for (int j = 0; j < 25; j++) {
            float wv = sim[i*26 + j];
            sv += wv * vs[c*25 + j];
            se += wv * rv[c*49 + (i - j + 24)];
        }
        float ri = rinv[i];
        sv *= ri; se *= ri;
        sob[(2*c)*25 + i]   = sv;
        sob[(2*c+1)*25 + i] = se;
        svsh[c*25 + i] = sv;
        sesh[c*25 + i] = se;
    }
    __syncthreads();
    // per-channel stats: 64 threads each reduce 25 staged values (no contention)
    if (tid < 64) {
        int c = tid >> 1;
        const float* src = (tid & 1) ? (sesh + c*25) : (svsh + c*25);
        float s = 0.f, sq = 0.f;
#pragma unroll
        for (int i = 0; i < 25; i++) { float v = src[i]; s += v; sq += v*v; }
        int ch = gb + 2*c + (tid & 1);
        atomicAdd(&g_osum[ch], s);
        atomicAdd(&g_osq[ch], sq);
    }
}

// ---------------- K8: out = x * (1 + sigmoid(o));  MLP=8 streaming --------------
__global__ void __launch_bounds__(400) k8_out(const float* __restrict__ x,
                                              float* __restrict__ out,
                                              const float* __restrict__ og,
                                              const float* __restrict__ ob) {
    __shared__ float msh[8][25];
    int tid = threadIdx.x;
    int sg = tid / 100, p = tid % 100;
    int s0 = blockIdx.x * 8 + sg, s1 = s0 + 4;
    if (p < 50) {                                   // gate for this group's two slabs
        int which = p / 25, pv = p % 25;
        int slab = which ? s1 : s0;
        int n = slab >> 8, c = slab & 255;
        int ch0 = 2*c, ch1 = ch0 + 1;
        float m0 = g_osum[ch0] * (1.f/1600.f);
        float v0 = g_osq[ch0] * (1.f/1600.f) - m0*m0;
        float sc0 = rsqrtf(v0 + EPSV) * og[ch0];
        float b0 = ob[ch0] - m0*sc0;
        float m1 = g_osum[ch1] * (1.f/1600.f);
        float v1 = g_osq[ch1] * (1.f/1600.f) - m1*m1;
        float sc1 = rsqrtf(v1 + EPSV) * og[ch1];
        float b1 = ob[ch1] - m1*sc1;
        const float* sbp = g_so + n*12800 + ch0*25;
        float t = (sbp[pv]*sc0 + b0) + (sbp[25+pv]*sc1 + b1);
        msh[sg + 4*which][pv] = 1.f + 1.f/(1.f + expf(-t));
    }
    __syncthreads();
    int f0 = 4*p;
    int i0 = f0 % 25, i1 = (f0+1) % 25, i2 = (f0+2) % 25, i3 = (f0+3) % 25;
    float a0 = msh[sg][i0], a1 = msh[sg][i1], a2 = msh[sg][i2], a3 = msh[sg][i3];
    float b0m = msh[sg+4][i0], b1m = msh[sg+4][i1], b2m = msh[sg+4][i2], b3m = msh[sg+4][i3];
    const float4* xa = (const float4*)(x + s0*1600) + p;
    const float4* xb = (const float4*)(x + s1*1600) + p;
    float4 x0 = xa[0], x1 = xa[100], x2 = xa[200], x3 = xa[300];
    float4 y0 = xb[0], y1 = xb[100], y2 = xb[200], y3 = xb[300];
    float4* oa = (float4*)(out + s0*1600) + p;
    float4* obp = (float4*)(out + s1*1600) + p;
    oa[0]   = make_float4(x0.x*a0, x0.y*a1, x0.z*a2, x0.w*a3);
    oa[100] = make_float4(x1.x*a0, x1.y*a1, x1.z*a2, x1.w*a3);
    oa[200] = make_float4(x2.x*a0, x2.y*a1, x2.z*a2, x2.w*a3);
    oa[300] = make_float4(x3.x*a0, x3.y*a1, x3.z*a2, x3.w*a3);
    obp[0]   = make_float4(y0.x*b0m, y0.y*b1m, y0.z*b2m, y0.w*b3m);
    obp[100] = make_float4(y1.x*b0m, y1.y*b1m, y1.z*b2m, y1.w*b3m);
    obp[200] = make_float4(y2.x*b0m, y2.y*b1m, y2.z*b2m, y2.w*b3m);
    obp[300] = make_float4(y3.x*b0m, y3.y*b1m, y3.z*b2m, y3.w*b3m);
}

// ---------------- launch ---------------------------------------------------------
extern "C" void kernel_launch(void* const* d_in, const int* in_sizes, int n_in,
                              void* d_out, int out_size) {
    const float* x   = (const float*)d_in[0];
    const float* w   = (const float*)d_in[1];
    const float* rel = (const float*)d_in[2];
    const float* qg  = (const float*)d_in[3];
    const float* qb  = (const float*)d_in[4];
    const float* sg  = (const float*)d_in[5];
    const float* sbb = (const float*)d_in[6];
    const float* og  = (const float*)d_in[7];
    const float* ob  = (const float*)d_in[8];
    float* out = (float*)d_out;

    k1_mean<<<2048, 400>>>(x);
    k2_qkv<<<128, 256>>>(w);
    k4_sim<<<512, 256>>>(rel, qg, qb);
    k6_attn<<<512, 256>>>(rel, qg, qb, sg, sbb);
    k8_out<<<2048, 400>>>(x, out, og, ob);
}

// round 5
// speedup vs baseline: 1.4823x; 1.0190x over previous
#include <cuda_runtime.h>

#define EPSV 1e-5f

// ---------------- scratch (static device globals; no runtime alloc) -------------
__device__ float g_y[64*256*25];               // mean over T
__device__ float g_qkv[64*512*25];             // raw qkv projection
__device__ float g_qsum[512], g_qsq[512];
__device__ float g_stk[64*8*3*625];            // qk/qr/kr raw
__device__ float g_ssum[24], g_ssq[24];
__device__ float g_so[64*512*25];              // sv/sve interleaved
__device__ float g_osum[512], g_osq[512];

// ---------------- K1: y[n,c,v] = mean_t x[n,c,t,v]  (float4, MLP=8) -------------
__global__ void __launch_bounds__(400) k1_mean(const float* __restrict__ x) {
    __shared__ float redA[1600], redB[1600];
    int tid = threadIdx.x;
    if (blockIdx.x == 0) {
        for (int i = tid; i < 512; i += 400) { g_qsum[i]=0.f; g_qsq[i]=0.f; g_osum[i]=0.f; g_osq[i]=0.f; }
        if (tid < 24) { g_ssum[tid]=0.f; g_ssq[tid]=0.f; }
    }
    int sg = tid / 100, p = tid % 100;
    int s0 = blockIdx.x * 8 + sg, s1 = s0 + 4;
    const float4* xa = (const float4*)(x + s0 * 1600) + p;
    const float4* xb = (const float4*)(x + s1 * 1600) + p;
    float4 a0 = xa[0], a1 = xa[100], a2 = xa[200], a3 = xa[300];
    float4 b0 = xb[0], b1 = xb[100], b2 = xb[200], b3 = xb[300];
    float4 sa = make_float4(a0.x+a1.x+a2.x+a3.x, a0.y+a1.y+a2.y+a3.y,
                            a0.z+a1.z+a2.z+a3.z, a0.w+a1.w+a2.w+a3.w);
    float4 sb = make_float4(b0.x+b1.x+b2.x+b3.x, b0.y+b1.y+b2.y+b3.y,
                            b0.z+b1.z+b2.z+b3.z, b0.w+b1.w+b2.w+b3.w);
    ((float4*)redA)[sg*100 + p] = sa;
    ((float4*)redB)[sg*100 + p] = sb;
    __syncthreads();
    if (p < 25) {
        float t0 = 0.f, t1 = 0.f;
#pragma unroll
        for (int r = 0; r < 16; r++) { t0 += redA[sg*400 + p + 25*r]; t1 += redB[sg*400 + p + 25*r]; }
        g_y[s0*25 + p] = t0 * (1.0f/64.0f);
        g_y[s1*25 + p] = t1 * (1.0f/64.0f);
    }
}

// ---------------- K2: qkv[n,o,v] = sum_c w[o,c]*y[n,c,v] + BN partial stats -----
__global__ void __launch_bounds__(256) k2_qkv(const float* __restrict__ w) {
    __shared__ __align__(16) float ysm[256*28];
    __shared__ float wsm[16*256];
    int tid = threadIdx.x;
    int n = blockIdx.x >> 1, half = blockIdx.x & 1;

    for (int i = tid; i < 256*28; i += 256) ysm[i] = 0.f;
    __syncthreads();
    const float* yb = g_y + n * (256*25);
    for (int i = tid; i < 256*25; i += 256) { int c = i/25, v = i - c*25; ysm[c*28 + v] = yb[i]; }

    unsigned long long acc[14];
#pragma unroll
    for (int q = 0; q < 14; q++) acc[q] = 0ull;

    int o = half * 256 + tid;
    for (int c0 = 0; c0 < 256; c0 += 16) {
        __syncthreads();
        for (int i = tid; i < 4096; i += 256) {
            int ol = i >> 4, cc = i & 15;
            wsm[cc*256 + ol] = w[(half*256 + ol)*256 + c0 + cc];
        }
        __syncthreads();
#pragma unroll
        for (int cc = 0; cc < 16; cc++) {
            float wv = wsm[cc*256 + tid];
            unsigned long long w2; asm("mov.b64 %0,{%1,%1};" : "=l"(w2) : "f"(wv));
            const ulonglong2* yr = (const ulonglong2*)(ysm + (c0 + cc)*28);
#pragma unroll
            for (int q = 0; q < 7; q++) {
                ulonglong2 yv = yr[q];
                asm("fma.rn.f32x2 %0,%1,%2,%0;" : "+l"(acc[2*q])   : "l"(w2), "l"(yv.x));
                asm("fma.rn.f32x2 %0,%1,%2,%0;" : "+l"(acc[2*q+1]) : "l"(w2), "l"(yv.y));
            }
        }
    }
    float vals[28];
#pragma unroll
    for (int q = 0; q < 14; q++)
        asm("mov.b64 {%0,%1},%2;" : "=f"(vals[2*q]), "=f"(vals[2*q+1]) : "l"(acc[q]));

    float s = 0.f, sq = 0.f;
    float* qb = g_qkv + n*(512*25) + o*25;
#pragma unroll
    for (int v = 0; v < 25; v++) { float q = vals[v]; qb[v] = q; s += q; sq += q*q; }
    atomicAdd(&g_qsum[o], s);
    atomicAdd(&g_qsq[o], sq);
}

// ---------------- K4: {qk,qr,kr};  2 blocks per (n,g), each ~313 elements -------
__global__ void __launch_bounds__(256) k4_sim(const float* __restrict__ rel,
                                              const float* __restrict__ qg,
                                              const float* __restrict__ qbb) {
    __shared__ float qs[400], ks[400], rs[1568];
    __shared__ float sc_[32], bi_[32];
    __shared__ float ssum[3], ssq[3];
    int tid = threadIdx.x;
    int ng = blockIdx.x >> 1, he = blockIdx.x & 1;   // element-half
    int n = ng >> 3, g = ng & 7;
    int gb = g * 64;
    if (tid < 32) {
        int ch = gb + tid;
        float m = g_qsum[ch] * (1.f/1600.f);
        float var = g_qsq[ch] * (1.f/1600.f) - m*m;
        float s = rsqrtf(var + EPSV) * qg[ch];
        sc_[tid] = s; bi_[tid] = qbb[ch] - m*s;
    }
    if (tid < 3) { ssum[tid] = 0.f; ssq[tid] = 0.f; }
    __syncthreads();
    const float* qkvb = g_qkv + n*12800 + gb*25;
    for (int i = tid; i < 400; i += 256) { int c = i/25; qs[i] = qkvb[i]     *sc_[c]    + bi_[c]; }
    for (int i = tid; i < 400; i += 256) { int c = i/25; ks[i] = qkvb[400+i] *sc_[16+c] + bi_[16+c]; }
    for (int i = tid; i < 1568; i += 256) rs[i] = rel[i];
    __syncthreads();

    float sa=0.f, qa=0.f, sb2=0.f, qb2=0.f, sc2=0.f, qc2=0.f;
    float* ob = g_stk + ng * 1875;
    int e0 = he * 313, e1 = min(625, e0 + 313);
    for (int e = e0 + tid; e < e1; e += 256) {
        int i = e/25, j = e - i*25;
        float a=0.f, b=0.f, c2=0.f;
        int di = i - j + 24, dj = j - i + 24;
#pragma unroll
        for (int c = 0; c < 16; c++) {
            float qv = qs[c*25 + i], kv = ks[c*25 + j];
            a  += qv * kv;
            b  += qv * rs[c*49 + di];
            c2 += kv * rs[(16+c)*49 + dj];
        }
        ob[e] = a; ob[625+e] = b; ob[1250+e] = c2;
        sa += a; qa += a*a; sb2 += b; qb2 += b*b; sc2 += c2; qc2 += c2*c2;
    }
#pragma unroll
    for (int d = 16; d > 0; d >>= 1) {
        sa  += __shfl_xor_sync(0xffffffffu, sa,  d);
        qa  += __shfl_xor_sync(0xffffffffu, qa,  d);
        sb2 += __shfl_xor_sync(0xffffffffu, sb2, d);
        qb2 += __shfl_xor_sync(0xffffffffu, qb2, d);
        sc2 += __shfl_xor_sync(0xffffffffu, sc2, d);
        qc2 += __shfl_xor_sync(0xffffffffu, qc2, d);
    }
    if ((tid & 31) == 0) {
        atomicAdd(&ssum[0], sa);  atomicAdd(&ssq[0], qa);
        atomicAdd(&ssum[1], sb2); atomicAdd(&ssq[1], qb2);
        atomicAdd(&ssum[2], sc2); atomicAdd(&ssq[2], qc2);
    }
    __syncthreads();
    if (tid < 3) { atomicAdd(&g_ssum[tid*8 + g], ssum[tid]); atomicAdd(&g_ssq[tid*8 + g], ssq[tid]); }
}

// ---------------- K6: softmax + sv/sve;  2 blocks per (n,g), 16 channels each ---
__global__ void __launch_bounds__(256) k6_attn(const float* __restrict__ rel,
                                               const float* __restrict__ qg,
                                               const float* __restrict__ qbb,
                                               const float* __restrict__ sg,
                                               const float* __restrict__ sbb) {
    __shared__ float sim[25*26];
    __shared__ float vs[400], rv[784], rowsum[25], rinv[25];
    __shared__ float svsh[400], sesh[400];
    __shared__ float vsc[16], vbi[16], ssc[3], sbi[3];
    int tid = threadIdx.x;
    int ng = blockIdx.x >> 1, hc = blockIdx.x & 1;   // channel-half
    int n = ng >> 3, g = ng & 7;
    int gb = g * 64;
    int cb = gb + 32 + hc * 16;                      // first v-channel this block owns

    if (tid < 16) {                                  // BN finalize for our 16 v channels
        int ch = cb + tid;
        float m = g_qsum[ch] * (1.f/1600.f);
        float var = g_qsq[ch] * (1.f/1600.f) - m*m;
        float s = rsqrtf(var + EPSV) * qg[ch];
        vsc[tid] = s; vbi[tid] = qbb[ch] - m*s;
    } else if (tid < 19) {                           // sim BN finalize (3 channels)
        int t2 = tid - 16, ch = t2*8 + g;
        float m = g_ssum[ch] * (1.f/40000.f);
        float var = g_ssq[ch] * (1.f/40000.f) - m*m;
        float s = rsqrtf(var + EPSV) * sg[ch];
        ssc[t2] = s; sbi[t2] = sbb[ch] - m*s;
    }
    if (tid < 25) rowsum[tid] = 0.f;
    __syncthreads();

    const float* qkvb = g_qkv + n*12800 + cb*25;
    for (int i = tid; i < 400; i += 256) { int c = i/25; vs[i] = qkvb[i]*vsc[c] + vbi[c]; }
    for (int i = tid; i < 784; i += 256) rv[i] = rel[(32 + hc*16)*49 + i];

    const float* sb = g_stk + ng * 1875;
    for (int e = tid; e < 625; e += 256) {
        int i = e/25, j = e - i*25;
        float s = sb[e]*ssc[0] + sbi[0] + sb[625+e]*ssc[1] + sbi[1] + sb[1250+e]*ssc[2] + sbi[2];
        float ex = __expf(s);
        sim[i*26 + j] = ex;
        atomicAdd(&rowsum[i], ex);
    }
    __syncthreads();
    if (tid < 25) rinv[tid] = 1.f / rowsum[tid];
    __syncthreads();

    // store base: group base gb*25 plus (sv,se)-pair offset for our channel half.
    // our local channel c maps to group v-channel (hc*16 + c); pair channels are
    // 2*(hc*16 + c) and 2*(hc*16 + c)+1 within [0,64).  base = (gb + 32*hc)*25.
    float* sob = g_so + n*12800 + (gb + 32*hc)*25;
    for (int idx = tid; idx < 400; idx += 256) {
        int c = idx/25, i = idx - c*25;
        float sv = 0.f, se = 0.f;
#pragma unroll
        for (int j = 0; j < 25; j++) {
            float wv = sim[i*26 + j];
            sv += wv * vs[c*25 + j];
            se += wv * rv[c*49 + (i - j + 24)];
        }
        float ri = rinv[i];
        sv *= ri; se *= ri;
        sob[(2*c)*25 + i]   = sv;
        sob[(2*c+1)*25 + i] = se;
        svsh[c*25 + i] = sv;
        sesh[c*25 + i] = se;
    }
    __syncthreads();
    if (tid < 32) {
        int c = tid >> 1;
        const float* src = (tid & 1) ? (sesh + c*25) : (svsh + c*25);
        float s = 0.f, sq = 0.f;
#pragma unroll
        for (int i = 0; i < 25; i++) { float v = src[i]; s += v; sq += v*v; }
        int ch = gb + 32*hc + 2*c + (tid & 1);
        atomicAdd(&g_osum[ch], s);
        atomicAdd(&g_osq[ch], sq);
    }
}

// ---------------- K8: out = x * (1 + sigmoid(o));  MLP=8 streaming --------------
__global__ void __launch_bounds__(400) k8_out(const float* __restrict__ x,
                                              float* __restrict__ out,
                                              const float* __restrict__ og,
                                              const float* __restrict__ ob) {
    __shared__ float msh[8][25];
    int tid = threadIdx.x;
    int sg = tid / 100, p = tid % 100;
    int s0 = blockIdx.x * 8 + sg, s1 = s0 + 4;
    if (p < 50) {
        int which = p / 25, pv = p % 25;
        int slab = which ? s1 : s0;
        int n = slab >> 8, c = slab & 255;
        int ch0 = 2*c, ch1 = ch0 + 1;
        float m0 = g_osum[ch0] * (1.f/1600.f);
        float v0 = g_osq[ch0] * (1.f/1600.f) - m0*m0;
        float sc0 = rsqrtf(v0 + EPSV) * og[ch0];
        float b0 = ob[ch0] - m0*sc0;
        float m1 = g_osum[ch1] * (1.f/1600.f);
        float v1 = g_osq[ch1] * (1.f/1600.f) - m1*m1;
        float sc1 = rsqrtf(v1 + EPSV) * og[ch1];
        float b1 = ob[ch1] - m1*sc1;
        const float* sbp = g_so + n*12800 + ch0*25;
        float t = (sbp[pv]*sc0 + b0) + (sbp[25+pv]*sc1 + b1);
        msh[sg + 4*which][pv] = 1.f + 1.f/(1.f + expf(-t));
    }
    __syncthreads();
    int f0 = 4*p;
    int i0 = f0 % 25, i1 = (f0+1) % 25, i2 = (f0+2) % 25, i3 = (f0+3) % 25;
    float a0 = msh[sg][i0], a1 = msh[sg][i1], a2 = msh[sg][i2], a3 = msh[sg][i3];
    float b0m = msh[sg+4][i0], b1m = msh[sg+4][i1], b2m = msh[sg+4][i2], b3m = msh[sg+4][i3];
    const float4* xa = (const float4*)(x + s0*1600) + p;
    const float4* xb = (const float4*)(x + s1*1600) + p;
    float4 x0 = xa[0], x1 = xa[100], x2 = xa[200], x3 = xa[300];
    float4 y0 = xb[0], y1 = xb[100], y2 = xb[200], y3 = xb[300];
    float4* oa = (float4*)(out + s0*1600) + p;
    float4* obp = (float4*)(out + s1*1600) + p;
    oa[0]   = make_float4(x0.x*a0, x0.y*a1, x0.z*a2, x0.w*a3);
    oa[100] = make_float4(x1.x*a0, x1.y*a1, x1.z*a2, x1.w*a3);
    oa[200] = make_float4(x2.x*a0, x2.y*a1, x2.z*a2, x2.w*a3);
    oa[300] = make_float4(x3.x*a0, x3.y*a1, x3.z*a2, x3.w*a3);
    obp[0]   = make_float4(y0.x*b0m, y0.y*b1m, y0.z*b2m, y0.w*b3m);
    obp[100] = make_float4(y1.x*b0m, y1.y*b1m, y1.z*b2m, y1.w*b3m);
    obp[200] = make_float4(y2.x*b0m, y2.y*b1m, y2.z*b2m, y2.w*b3m);
    obp[300] = make_float4(y3.x*b0m, y3.y*b1m, y3.z*b2m, y3.w*b3m);
}

// ---------------- launch ---------------------------------------------------------
extern "C" void kernel_launch(void* const* d_in, const int* in_sizes, int n_in,
                              void* d_out, int out_size) {
    const float* x   = (const float*)d_in[0];
    const float* w   = (const float*)d_in[1];
    const float* rel = (const float*)d_in[2];
    const float* qg  = (const float*)d_in[3];
    const float* qb  = (const float*)d_in[4];
    const float* sg  = (const float*)d_in[5];
    const float* sbb = (const float*)d_in[6];
    const float* og  = (const float*)d_in[7];
    const float* ob  = (const float*)d_in[8];
    float* out = (float*)d_out;

    k1_mean<<<2048, 400>>>(x);
    k2_qkv<<<128, 256>>>(w);
    k4_sim<<<1024, 256>>>(rel, qg, qb);
    k6_attn<<<1024, 256>>>(rel, qg, qb, sg, sbb);
    k8_out<<<2048, 400>>>(x, out, og, ob);
}

// round 6
// speedup vs baseline: 1.5451x; 1.0423x over previous
#include <cuda_runtime.h>

#define EPSV 1e-5f

// ---------------- scratch (static device globals; no runtime alloc) -------------
__device__ float g_y[64*256*25];               // mean over T
__device__ float g_qkv[64*512*25];             // raw qkv projection
__device__ float g_qsum[512], g_qsq[512];
__device__ float g_stk[64*8*3*625];            // qk/qr/kr raw
__device__ float g_ssum[24], g_ssq[24];
__device__ float g_so[64*512*25];              // sv/sve interleaved
__device__ float g_osum[512], g_osq[512];

// ---------------- K1: y[n,c,v] = mean_t x[n,c,t,v]  (float4, MLP=8) -------------
__global__ void __launch_bounds__(400) k1_mean(const float* __restrict__ x) {
    __shared__ float redA[1600], redB[1600];
    int tid = threadIdx.x;
    if (blockIdx.x == 0) {
        for (int i = tid; i < 512; i += 400) { g_qsum[i]=0.f; g_qsq[i]=0.f; g_osum[i]=0.f; g_osq[i]=0.f; }
        if (tid < 24) { g_ssum[tid]=0.f; g_ssq[tid]=0.f; }
    }
    int sg = tid / 100, p = tid % 100;
    int s0 = blockIdx.x * 8 + sg, s1 = s0 + 4;
    const float4* xa = (const float4*)(x + s0 * 1600) + p;
    const float4* xb = (const float4*)(x + s1 * 1600) + p;
    float4 a0 = xa[0], a1 = xa[100], a2 = xa[200], a3 = xa[300];
    float4 b0 = xb[0], b1 = xb[100], b2 = xb[200], b3 = xb[300];
    float4 sa = make_float4(a0.x+a1.x+a2.x+a3.x, a0.y+a1.y+a2.y+a3.y,
                            a0.z+a1.z+a2.z+a3.z, a0.w+a1.w+a2.w+a3.w);
    float4 sb = make_float4(b0.x+b1.x+b2.x+b3.x, b0.y+b1.y+b2.y+b3.y,
                            b0.z+b1.z+b2.z+b3.z, b0.w+b1.w+b2.w+b3.w);
    ((float4*)redA)[sg*100 + p] = sa;
    ((float4*)redB)[sg*100 + p] = sb;
    __syncthreads();
    if (p < 25) {
        float t0 = 0.f, t1 = 0.f;
#pragma unroll
        for (int r = 0; r < 16; r++) { t0 += redA[sg*400 + p + 25*r]; t1 += redB[sg*400 + p + 25*r]; }
        g_y[s0*25 + p] = t0 * (1.0f/64.0f);
        g_y[s1*25 + p] = t1 * (1.0f/64.0f);
    }
}

// ---------------- K2: qkv[n,o,v] = sum_c w[o,c]*y[n,c,v] + BN partial stats -----
__global__ void __launch_bounds__(256) k2_qkv(const float* __restrict__ w) {
    __shared__ __align__(16) float ysm[256*28];
    __shared__ float wsm[16*256];
    int tid = threadIdx.x;
    int n = blockIdx.x >> 1, half = blockIdx.x & 1;

    for (int i = tid; i < 256*28; i += 256) ysm[i] = 0.f;
    __syncthreads();
    const float* yb = g_y + n * (256*25);
    for (int i = tid; i < 256*25; i += 256) { int c = i/25, v = i - c*25; ysm[c*28 + v] = yb[i]; }

    unsigned long long acc[14];
#pragma unroll
    for (int q = 0; q < 14; q++) acc[q] = 0ull;

    int o = half * 256 + tid;
    for (int c0 = 0; c0 < 256; c0 += 16) {
        __syncthreads();
        for (int i = tid; i < 4096; i += 256) {
            int ol = i >> 4, cc = i & 15;
            wsm[cc*256 + ol] = w[(half*256 + ol)*256 + c0 + cc];
        }
        __syncthreads();
#pragma unroll
        for (int cc = 0; cc < 16; cc++) {
            float wv = wsm[cc*256 + tid];
            unsigned long long w2; asm("mov.b64 %0,{%1,%1};" : "=l"(w2) : "f"(wv));
            const ulonglong2* yr = (const ulonglong2*)(ysm + (c0 + cc)*28);
#pragma unroll
            for (int q = 0; q < 7; q++) {
                ulonglong2 yv = yr[q];
                asm("fma.rn.f32x2 %0,%1,%2,%0;" : "+l"(acc[2*q])   : "l"(w2), "l"(yv.x));
                asm("fma.rn.f32x2 %0,%1,%2,%0;" : "+l"(acc[2*q+1]) : "l"(w2), "l"(yv.y));
            }
        }
    }
    float vals[28];
#pragma unroll
    for (int q = 0; q < 14; q++)
        asm("mov.b64 {%0,%1},%2;" : "=f"(vals[2*q]), "=f"(vals[2*q+1]) : "l"(acc[q]));

    float s = 0.f, sq = 0.f;
    float* qb = g_qkv + n*(512*25) + o*25;
#pragma unroll
    for (int v = 0; v < 25; v++) { float q = vals[v]; qb[v] = q; s += q; sq += q*q; }
    atomicAdd(&g_qsum[o], s);
    atomicAdd(&g_qsq[o], sq);
}

// ---------------- K4: {qk,qr,kr} per (n,g), 512 threads, no duplication ---------
__global__ void __launch_bounds__(512) k4_sim(const float* __restrict__ rel,
                                              const float* __restrict__ qg,
                                              const float* __restrict__ qbb) {
    __shared__ float qs[400], ks[400], rs[1568];
    __shared__ float sc_[32], bi_[32];
    __shared__ float ssum[3], ssq[3];
    int tid = threadIdx.x;
    int n = blockIdx.x >> 3, g = blockIdx.x & 7;
    int gb = g * 64;
    if (tid < 32) {
        int ch = gb + tid;
        float m = g_qsum[ch] * (1.f/1600.f);
        float var = g_qsq[ch] * (1.f/1600.f) - m*m;
        float s = rsqrtf(var + EPSV) * qg[ch];
        sc_[tid] = s; bi_[tid] = qbb[ch] - m*s;
    }
    if (tid >= 64 && tid < 67) { ssum[tid-64] = 0.f; ssq[tid-64] = 0.f; }
    __syncthreads();
    const float* qkvb = g_qkv + n*12800 + gb*25;
    for (int i = tid; i < 400; i += 512) { int c = i/25; qs[i] = qkvb[i]     *sc_[c]    + bi_[c]; }
    for (int i = tid; i < 400; i += 512) { int c = i/25; ks[i] = qkvb[400+i] *sc_[16+c] + bi_[16+c]; }
    for (int i = tid; i < 1568; i += 512) rs[i] = rel[i];
    __syncthreads();

    float sa=0.f, qa=0.f, sb2=0.f, qb2=0.f, sc2=0.f, qc2=0.f;
    float* ob = g_stk + blockIdx.x * 1875;
    for (int e = tid; e < 625; e += 512) {
        int i = e/25, j = e - i*25;
        float a=0.f, b=0.f, c2=0.f;
        int di = i - j + 24, dj = j - i + 24;
#pragma unroll
        for (int c = 0; c < 16; c++) {
            float qv = qs[c*25 + i], kv = ks[c*25 + j];
            a  += qv * kv;
            b  += qv * rs[c*49 + di];
            c2 += kv * rs[(16+c)*49 + dj];
        }
        ob[e] = a; ob[625+e] = b; ob[1250+e] = c2;
        sa += a; qa += a*a; sb2 += b; qb2 += b*b; sc2 += c2; qc2 += c2*c2;
    }
#pragma unroll
    for (int d = 16; d > 0; d >>= 1) {
        sa  += __shfl_xor_sync(0xffffffffu, sa,  d);
        qa  += __shfl_xor_sync(0xffffffffu, qa,  d);
        sb2 += __shfl_xor_sync(0xffffffffu, sb2, d);
        qb2 += __shfl_xor_sync(0xffffffffu, qb2, d);
        sc2 += __shfl_xor_sync(0xffffffffu, sc2, d);
        qc2 += __shfl_xor_sync(0xffffffffu, qc2, d);
    }
    if ((tid & 31) == 0) {
        atomicAdd(&ssum[0], sa);  atomicAdd(&ssq[0], qa);
        atomicAdd(&ssum[1], sb2); atomicAdd(&ssq[1], qb2);
        atomicAdd(&ssum[2], sc2); atomicAdd(&ssq[2], qc2);
    }
    __syncthreads();
    if (tid < 3) { atomicAdd(&g_ssum[tid*8 + g], ssum[tid]); atomicAdd(&g_ssq[tid*8 + g], ssq[tid]); }
}

// ---------------- K6: softmax + sv/sve per (n,g), 512 threads, exp once ---------
__global__ void __launch_bounds__(512) k6_attn(const float* __restrict__ rel,
                                               const float* __restrict__ qg,
                                               const float* __restrict__ qbb,
                                               const float* __restrict__ sg,
                                               const float* __restrict__ sbb) {
    __shared__ float sim[25*26];
    __shared__ float vs[800], rv[1568], rowsum[25], rinv[25];
    __shared__ float svsh[800], sesh[800];
    __shared__ float vsc[32], vbi[32], ssc[3], sbi[3];
    int tid = threadIdx.x;
    int n = blockIdx.x >> 3, g = blockIdx.x & 7;
    int gb = g * 64;

    if (tid < 32) {                                 // BN finalize for 32 v channels
        int ch = gb + 32 + tid;
        float m = g_qsum[ch] * (1.f/1600.f);
        float var = g_qsq[ch] * (1.f/1600.f) - m*m;
        float s = rsqrtf(var + EPSV) * qg[ch];
        vsc[tid] = s; vbi[tid] = qbb[ch] - m*s;
    } else if (tid < 35) {                          // sim BN finalize (3 channels)
        int t2 = tid - 32, ch = t2*8 + g;
        float m = g_ssum[ch] * (1.f/40000.f);
        float var = g_ssq[ch] * (1.f/40000.f) - m*m;
        float s = rsqrtf(var + EPSV) * sg[ch];
        ssc[t2] = s; sbi[t2] = sbb[ch] - m*s;
    } else if (tid >= 64 && tid < 89) rowsum[tid-64] = 0.f;
    __syncthreads();

    const float* qkvb = g_qkv + n*12800 + (gb + 32)*25;
    for (int i = tid; i < 800; i += 512) { int c = i/25; vs[i] = qkvb[i]*vsc[c] + vbi[c]; }
    for (int i = tid; i < 1568; i += 512) rv[i] = rel[32*49 + i];

    // single exp pass; BN'd logits are O(few sigma) so no max shift needed
    const float* sb = g_stk + blockIdx.x * 1875;
    for (int e = tid; e < 625; e += 512) {
        int i = e/25, j = e - i*25;
        float s = sb[e]*ssc[0] + sbi[0] + sb[625+e]*ssc[1] + sbi[1] + sb[1250+e]*ssc[2] + sbi[2];
        float ex = __expf(s);
        sim[i*26 + j] = ex;
        atomicAdd(&rowsum[i], ex);
    }
    __syncthreads();
    if (tid < 25) rinv[tid] = 1.f / rowsum[tid];
    __syncthreads();

    float* sob = g_so + n*12800 + gb*25;
    for (int idx = tid; idx < 800; idx += 512) {
        int c = idx/25, i = idx - c*25;
        float sv = 0.f, se = 0.f;
#pragma unroll
        for (int j = 0; j < 25; j++) {
            float wv = sim[i*26 + j];
            sv += wv * vs[c*25 + j];
            se += wv * rv[c*49 + (i - j + 24)];
        }
        float ri = rinv[i];
        sv *= ri; se *= ri;
        sob[(2*c)*25 + i]   = sv;
        sob[(2*c+1)*25 + i] = se;
        svsh[c*25 + i] = sv;
        sesh[c*25 + i] = se;
    }
    __syncthreads();
    if (tid < 64) {
        int c = tid >> 1;
        const float* src = (tid & 1) ? (sesh + c*25) : (svsh + c*25);
        float s = 0.f, sq = 0.f;
#pragma unroll
        for (int i = 0; i < 25; i++) { float v = src[i]; s += v; sq += v*v; }
        atomicAdd(&g_osum[gb + tid], s);
        atomicAdd(&g_osq[gb + tid], sq);
    }
}

// ---------------- K8: out = x * (1 + sigmoid(o));  MLP=8 streaming --------------
__global__ void __launch_bounds__(400) k8_out(const float* __restrict__ x,
                                              float* __restrict__ out,
                                              const float* __restrict__ og,
                                              const float* __restrict__ ob) {
    __shared__ float msh[8][25];
    int tid = threadIdx.x;
    int sg = tid / 100, p = tid % 100;
    int s0 = blockIdx.x * 8 + sg, s1 = s0 + 4;
    if (p < 50) {
        int which = p / 25, pv = p % 25;
        int slab = which ? s1 : s0;
        int n = slab >> 8, c = slab & 255;
        int ch0 = 2*c, ch1 = ch0 + 1;
        float m0 = g_osum[ch0] * (1.f/1600.f);
        float v0 = g_osq[ch0] * (1.f/1600.f) - m0*m0;
        float sc0 = rsqrtf(v0 + EPSV) * og[ch0];
        float b0 = ob[ch0] - m0*sc0;
        float m1 = g_osum[ch1] * (1.f/1600.f);
        float v1 = g_osq[ch1] * (1.f/1600.f) - m1*m1;
        float sc1 = rsqrtf(v1 + EPSV) * og[ch1];
        float b1 = ob[ch1] - m1*sc1;
        const float* sbp = g_so + n*12800 + ch0*25;
        float t = (sbp[pv]*sc0 + b0) + (sbp[25+pv]*sc1 + b1);
        msh[sg + 4*which][pv] = 1.f + 1.f/(1.f + expf(-t));
    }
    __syncthreads();
    int f0 = 4*p;
    int i0 = f0 % 25, i1 = (f0+1) % 25, i2 = (f0+2) % 25, i3 = (f0+3) % 25;
    float a0 = msh[sg][i0], a1 = msh[sg][i1], a2 = msh[sg][i2], a3 = msh[sg][i3];
    float b0m = msh[sg+4][i0], b1m = msh[sg+4][i1], b2m = msh[sg+4][i2], b3m = msh[sg+4][i3];
    const float4* xa = (const float4*)(x + s0*1600) + p;
    const float4* xb = (const float4*)(x + s1*1600) + p;
    float4 x0 = xa[0], x1 = xa[100], x2 = xa[200], x3 = xa[300];
    float4 y0 = xb[0], y1 = xb[100], y2 = xb[200], y3 = xb[300];
    float4* oa = (float4*)(out + s0*1600) + p;
    float4* obp = (float4*)(out + s1*1600) + p;
    oa[0]   = make_float4(x0.x*a0, x0.y*a1, x0.z*a2, x0.w*a3);
    oa[100] = make_float4(x1.x*a0, x1.y*a1, x1.z*a2, x1.w*a3);
    oa[200] = make_float4(x2.x*a0, x2.y*a1, x2.z*a2, x2.w*a3);
    oa[300] = make_float4(x3.x*a0, x3.y*a1, x3.z*a2, x3.w*a3);
    obp[0]   = make_float4(y0.x*b0m, y0.y*b1m, y0.z*b2m, y0.w*b3m);
    obp[100] = make_float4(y1.x*b0m, y1.y*b1m, y1.z*b2m, y1.w*b3m);
    obp[200] = make_float4(y2.x*b0m, y2.y*b1m, y2.z*b2m, y2.w*b3m);
    obp[300] = make_float4(y3.x*b0m, y3.y*b1m, y3.z*b2m, y3.w*b3m);
}

// ---------------- launch ---------------------------------------------------------
extern "C" void kernel_launch(void* const* d_in, const int* in_sizes, int n_in,
                              void* d_out, int out_size) {
    const float* x   = (const float*)d_in[0];
    const float* w   = (const float*)d_in[1];
    const float* rel = (const float*)d_in[2];
    const float* qg  = (const float*)d_in[3];
    const float* qb  = (const float*)d_in[4];
    const float* sg  = (const float*)d_in[5];
    const float* sbb = (const float*)d_in[6];
    const float* og  = (const float*)d_in[7];
    const float* ob  = (const float*)d_in[8];
    float* out = (float*)d_out;

    k1_mean<<<2048, 400>>>(x);
    k2_qkv<<<128, 256>>>(w);
    k4_sim<<<512, 512>>>(rel, qg, qb);
    k6_attn<<<512, 512>>>(rel, qg, qb, sg, sbb);
    k8_out<<<2048, 400>>>(x, out, og, ob);
}